// round 3
// baseline (speedup 1.0000x reference)
#include <cuda_runtime.h>
#include <math.h>

// Problem constants
#define Bsz 8192
#define Sdim 268
#define Hdim 1024
#define Rn 8
#define Adim 256

// Scratch (allocation-free: __device__ globals)
__device__ float g_h[(size_t)Bsz * Hdim];
__device__ float g_u[(size_t)Bsz * Hdim];
__device__ float g_v2[(size_t)Bsz * Adim];

#define BM 128
#define BN 128
#define BK 8
#define TM 8
#define TN 8

// Generic NT GEMM: C-like = A(MxK, lda) * Bm(NxK, ldb)^T, epilogue by mode.
// mode 0: h = relu(acc + s*W0[n,K] + c*W0[n,K+1] + bias[n])          (K1)
// mode 1: C = tanh(acc + bias[n])                                     (u = tanh(h W1^T + b1))
// mode 2: C = tanh(aux[m*ldc+n] + acc + bias[n])                      (h = tanh(h + u W2^T + b2))
// mode 3: C = acc + bias[n]                                           (core / v2)
// mode 5: C[m*ldc+n] += 0.1f*(acc + bias[n] - aux[m*268 + n])         (delta_h fuse)
__global__ __launch_bounds__(256) void gemm_nt(
    const float* __restrict__ A, int lda,
    const float* __restrict__ Bm, int ldb,
    const float* __restrict__ bias,
    const float* __restrict__ aux,
    float* __restrict__ C, int ldc,
    int M, int N, int K, int mode,
    const float* __restrict__ tptr)
{
    __shared__ float As[BK][BM];
    __shared__ float Bs[BK][BN];

    const int tid = threadIdx.x;
    const int bm = blockIdx.y * BM;
    const int bn = blockIdx.x * BN;
    const int tm = (tid / 16) * TM;
    const int tn = (tid % 16) * TN;

    float acc[TM][TN];
#pragma unroll
    for (int i = 0; i < TM; i++)
#pragma unroll
        for (int j = 0; j < TN; j++) acc[i][j] = 0.0f;

    const int arow = tid >> 1;        // 0..127
    const int acol = (tid & 1) * 4;   // 0 or 4

    for (int k0 = 0; k0 < K; k0 += BK) {
        // Load A tile (M rows always in range: M multiple of 128 here)
#pragma unroll
        for (int i = 0; i < 4; i++) {
            int kk = k0 + acol + i;
            float v = 0.0f;
            if (kk < K) v = A[(size_t)(bm + arow) * lda + kk];
            As[acol + i][arow] = v;
        }
        // Load B tile (guard N and K)
#pragma unroll
        for (int i = 0; i < 4; i++) {
            int kk = k0 + acol + i;
            int n = bn + arow;
            float v = 0.0f;
            if (kk < K && n < N) v = Bm[(size_t)n * ldb + kk];
            Bs[acol + i][arow] = v;
        }
        __syncthreads();

#pragma unroll
        for (int k = 0; k < BK; k++) {
            float ra[TM], rb[TN];
#pragma unroll
            for (int i = 0; i < TM; i++) ra[i] = As[k][tm + i];
#pragma unroll
            for (int j = 0; j < TN; j++) rb[j] = Bs[k][tn + j];
#pragma unroll
            for (int i = 0; i < TM; i++)
#pragma unroll
                for (int j = 0; j < TN; j++) acc[i][j] += ra[i] * rb[j];
        }
        __syncthreads();
    }

    // Epilogue
    float sv = 0.0f, cv = 0.0f;
    if (mode == 0) {
        float ang = tptr[0] * (2.0f * 3.14159265358979323846f / 24.0f);
        sv = sinf(ang);
        cv = cosf(ang);
    }

#pragma unroll
    for (int i = 0; i < TM; i++) {
        int m = bm + tm + i;
#pragma unroll
        for (int j = 0; j < TN; j++) {
            int n = bn + tn + j;
            if (n >= N) continue;
            float v = acc[i][j];
            size_t cidx = (size_t)m * ldc + n;
            if (mode == 0) {
                v += sv * Bm[(size_t)n * ldb + K] + cv * Bm[(size_t)n * ldb + K + 1] + bias[n];
                C[cidx] = fmaxf(v, 0.0f);
            } else if (mode == 1) {
                C[cidx] = tanhf(v + bias[n]);
            } else if (mode == 2) {
                C[cidx] = tanhf(aux[cidx] + v + bias[n]);
            } else if (mode == 3) {
                C[cidx] = v + bias[n];
            } else { // mode 5
                C[cidx] += 0.1f * (v + bias[n] - aux[(size_t)m * Sdim + n]);
            }
        }
    }
}

// Tiny local-enhancement path: per batch row. Z=8, E=4.
__global__ void loc_kernel(
    const float* __restrict__ state, float* __restrict__ out,
    const float* __restrict__ loc_proj_w, const float* __restrict__ loc_proj_b,
    const float* __restrict__ lp_in_w,   const float* __restrict__ lp_in_b,
    const float* __restrict__ lp_out_w,  const float* __restrict__ lp_out_b,
    const float* __restrict__ loc_back_w,const float* __restrict__ loc_back_b)
{
    int m = blockIdx.x * blockDim.x + threadIdx.x;
    if (m >= Bsz) return;

    float loc[8];
#pragma unroll
    for (int j = 0; j < 8; j++) loc[j] = state[(size_t)m * Sdim + Adim + j];

    float lp[4];
#pragma unroll
    for (int i = 0; i < 4; i++) {
        float a = loc_proj_b[i];
#pragma unroll
        for (int j = 0; j < 8; j++) a += loc_proj_w[i * 8 + j] * loc[j];
        lp[i] = a;
    }
    float v[4];
#pragma unroll
    for (int i = 0; i < 4; i++) {
        float a = lp_in_b[8 + i];
#pragma unroll
        for (int j = 0; j < 4; j++) a += lp_in_w[(8 + i) * 4 + j] * lp[j];
        v[i] = a;
    }
    float d[4];
#pragma unroll
    for (int i = 0; i < 4; i++) {
        float a = lp_out_b[i];
#pragma unroll
        for (int j = 0; j < 4; j++) a += lp_out_w[i * 4 + j] * v[j];
        d[i] = a - lp[i];
    }
#pragma unroll
    for (int i = 0; i < 8; i++) {
        float a = loc_back_b[i];
#pragma unroll
        for (int j = 0; j < 4; j++) a += loc_back_w[i * 4 + j] * d[j];
        out[(size_t)m * Sdim + Adim + i] += 0.1f * a;
    }
}

extern "C" void kernel_launch(void* const* d_in, const int* in_sizes, int n_in,
                              void* d_out, int out_size)
{
    const float* t         = (const float*)d_in[0];
    const float* state     = (const float*)d_in[1];
    const float* W0        = (const float*)d_in[2];
    const float* b0        = (const float*)d_in[3];
    const float* res_W1    = (const float*)d_in[4];
    const float* res_b1    = (const float*)d_in[5];
    const float* res_W2    = (const float*)d_in[6];
    const float* res_b2    = (const float*)d_in[7];
    const float* Wf        = (const float*)d_in[8];
    const float* bf        = (const float*)d_in[9];
    const float* lp_in_w   = (const float*)d_in[10];
    const float* lp_in_b   = (const float*)d_in[11];
    const float* lp_out_w  = (const float*)d_in[12];
    const float* lp_out_b  = (const float*)d_in[13];
    const float* ta_in_w   = (const float*)d_in[14];
    const float* ta_in_b   = (const float*)d_in[15];
    const float* ta_out_w  = (const float*)d_in[16];
    const float* ta_out_b  = (const float*)d_in[17];
    const float* loc_proj_w= (const float*)d_in[18];
    const float* loc_proj_b= (const float*)d_in[19];
    const float* loc_back_w= (const float*)d_in[20];
    const float* loc_back_b= (const float*)d_in[21];
    float* out = (float*)d_out;

    float *h, *u, *v2;
    cudaGetSymbolAddress((void**)&h,  g_h);
    cudaGetSymbolAddress((void**)&u,  g_u);
    cudaGetSymbolAddress((void**)&v2, g_v2);

    dim3 blk(256);
    const int MY = Bsz / BM; // 64

    // K1: h = relu(state @ W0[:, :268]^T + sin*W0[:,268] + cos*W0[:,269] + b0)
    gemm_nt<<<dim3(Hdim / BN, MY), blk>>>(state, Sdim, W0, Sdim + 2, b0, nullptr,
                                          h, Hdim, Bsz, Hdim, Sdim, 0, t);

    // Residual scan: 8 blocks, 2 GEMMs each
    for (int r = 0; r < Rn; r++) {
        const float* W1 = res_W1 + (size_t)r * Hdim * Hdim;
        const float* b1 = res_b1 + (size_t)r * Hdim;
        const float* W2 = res_W2 + (size_t)r * Hdim * Hdim;
        const float* b2 = res_b2 + (size_t)r * Hdim;
        // u = tanh(h @ W1^T + b1)
        gemm_nt<<<dim3(Hdim / BN, MY), blk>>>(h, Hdim, W1, Hdim, b1, nullptr,
                                              u, Hdim, Bsz, Hdim, Hdim, 1, nullptr);
        // h = tanh(h + u @ W2^T + b2)
        gemm_nt<<<dim3(Hdim / BN, MY), blk>>>(u, Hdim, W2, Hdim, b2, h,
                                              h, Hdim, Bsz, Hdim, Hdim, 2, nullptr);
    }

    // K4: out = h @ Wf^T + bf   (all 268 cols)
    gemm_nt<<<dim3((Sdim + BN - 1) / BN, MY), blk>>>(h, Hdim, Wf, Hdim, bf, nullptr,
                                                     out, Sdim, Bsz, Sdim, Hdim, 3, nullptr);

    // K5: v2 = h_part @ ta_in_w[512:768]^T + ta_in_b[512:768]
    gemm_nt<<<dim3(Adim / BN, MY), blk>>>(state, Sdim, ta_in_w + (size_t)2 * Adim * Adim, Adim,
                                          ta_in_b + 2 * Adim, nullptr,
                                          v2, Adim, Bsz, Adim, Adim, 3, nullptr);

    // K6: out[:, :256] += 0.1*((v2 @ ta_out_w^T + ta_out_b) - h_part)
    gemm_nt<<<dim3(Adim / BN, MY), blk>>>(v2, Adim, ta_out_w, Adim, ta_out_b, state,
                                          out, Sdim, Bsz, Adim, Adim, 5, nullptr);

    // K7: loc path — out[:, 256:264] += 0.1*delta_loc
    loc_kernel<<<Bsz / 256, 256>>>(state, out,
                                   loc_proj_w, loc_proj_b,
                                   lp_in_w, lp_in_b,
                                   lp_out_w, lp_out_b,
                                   loc_back_w, loc_back_b);
}

// round 5
// speedup vs baseline: 4.2497x; 4.2497x over previous
#include <cuda_runtime.h>
#include <cuda_bf16.h>
#include <cstdint>
#include <math.h>

// ---------------- problem constants ----------------
#define Bsz 8192
#define Sdim 268
#define Hdim 1024
#define Rn 8
#define Adim 256
#define SPADK 320           // state/W0 logical K padded to mult of 64 (of K'/3 granularity)

// Triple-K sizes (K' = 3*K logical)
#define KP_S   960          // 3*320
#define KP_H   3072         // 3*1024
#define KP_A   768          // 3*256

// ---------------- device scratch (allocation-free) ----------------
__device__ float         g_h[(size_t)Bsz * Hdim];            // f32 h (for residual add)
__device__ __nv_bfloat16 g_sp3[(size_t)Bsz * KP_S];          // state triple (A-side)
__device__ __nv_bfloat16 g_h3[(size_t)Bsz * KP_H];           // h triple (A-side)
__device__ __nv_bfloat16 g_u3[(size_t)Bsz * KP_H];           // u triple (A-side)
__device__ __nv_bfloat16 g_v23[(size_t)Bsz * KP_A];          // v2 triple (A-side)
__device__ __nv_bfloat16 g_w03[(size_t)Hdim * KP_S];         // W0 triple (B-side)
__device__ __nv_bfloat16 g_rw13[(size_t)Rn * Hdim * KP_H];
__device__ __nv_bfloat16 g_rw23[(size_t)Rn * Hdim * KP_H];
__device__ __nv_bfloat16 g_wf3[(size_t)Sdim * KP_H];
__device__ __nv_bfloat16 g_tain3[(size_t)Adim * KP_A];
__device__ __nv_bfloat16 g_taout3[(size_t)Adim * KP_A];

// ---------------- helpers ----------------
__device__ __forceinline__ void split_bf16(float x, __nv_bfloat16& hi, __nv_bfloat16& lo) {
    hi = __float2bfloat16(x);
    lo = __float2bfloat16(x - __bfloat162float(hi));
}
__device__ __forceinline__ uint32_t smem_u32(const void* p) {
    uint32_t a;
    asm("{ .reg .u64 t; cvta.to.shared.u64 t, %1; cvt.u32.u64 %0, t; }" : "=r"(a) : "l"(p));
    return a;
}
__device__ __forceinline__ void cp16(uint32_t dst, const void* src, uint32_t sz) {
    asm volatile("cp.async.cg.shared.global [%0], [%1], 16, %2;"
                 :: "r"(dst), "l"(src), "r"(sz) : "memory");
}
__device__ __forceinline__ void ldm4(uint32_t& r0, uint32_t& r1, uint32_t& r2, uint32_t& r3, uint32_t a) {
    asm volatile("ldmatrix.sync.aligned.m8n8.x4.shared.b16 {%0,%1,%2,%3}, [%4];"
                 : "=r"(r0), "=r"(r1), "=r"(r2), "=r"(r3) : "r"(a));
}
__device__ __forceinline__ void mma16816(float* d, const uint32_t* a, const uint32_t* b) {
    asm volatile("mma.sync.aligned.m16n8k16.row.col.f32.bf16.bf16.f32 "
                 "{%0,%1,%2,%3}, {%4,%5,%6,%7}, {%8,%9}, {%0,%1,%2,%3};"
                 : "+f"(d[0]), "+f"(d[1]), "+f"(d[2]), "+f"(d[3])
                 : "r"(a[0]), "r"(a[1]), "r"(a[2]), "r"(a[3]), "r"(b[0]), "r"(b[1]));
}

// ---------------- conversion kernels ----------------
// B-side triple: [hi, lo, hi]
__global__ void conv_w(const float* __restrict__ src, __nv_bfloat16* __restrict__ dst,
                       int rows, int src_ld, int src_cols, int Klog) {
    size_t n = (size_t)rows * Klog;
    size_t i = (size_t)blockIdx.x * blockDim.x + threadIdx.x;
    size_t stride = (size_t)gridDim.x * blockDim.x;
    for (; i < n; i += stride) {
        int r = (int)(i / Klog), k = (int)(i % Klog);
        float x = (k < src_cols) ? src[(size_t)r * src_ld + k] : 0.0f;
        __nv_bfloat16 hi, lo; split_bf16(x, hi, lo);
        size_t base = ((size_t)r * Klog + k) * 3;
        dst[base] = hi; dst[base + 1] = lo; dst[base + 2] = hi;
    }
}
// A-side triple: [hi, hi, lo]
__global__ void conv_a(const float* __restrict__ src, __nv_bfloat16* __restrict__ dst,
                       int rows, int src_ld, int src_cols, int Klog) {
    size_t n = (size_t)rows * Klog;
    size_t i = (size_t)blockIdx.x * blockDim.x + threadIdx.x;
    size_t stride = (size_t)gridDim.x * blockDim.x;
    for (; i < n; i += stride) {
        int r = (int)(i / Klog), k = (int)(i % Klog);
        float x = (k < src_cols) ? src[(size_t)r * src_ld + k] : 0.0f;
        __nv_bfloat16 hi, lo; split_bf16(x, hi, lo);
        size_t base = ((size_t)r * Klog + k) * 3;
        dst[base] = hi; dst[base + 1] = hi; dst[base + 2] = lo;
    }
}

// ---------------- HMMA GEMM: C(MxN) = A'(MxK') * B'(NxK')^T ----------------
// CTA 128x128, KC=64, double-buffered cp.async, 8 warps of 32x64.
// modes: 0 h=relu(D+sv*W0[n,268]+cv*W0[n,269]+bias) -> Cf + triple
//        1 tanh(D+bias)                              -> triple only
//        2 tanh(aux+D+bias)                          -> Cf + triple
//        3 D+bias                                    -> Cf (and triple if given)
//        5 Cf += 0.1*(D+bias - aux[m*aux_ld+n])
#define KC 64
#define ROWB 144                   // smem bytes per row (128 data + 16 pad)
#define TILEB (128 * ROWB)         // 18432 per operand tile
#define STAGEB (2 * TILEB)         // 36864
#define SMEM_DYN (2 * STAGEB)      // 73728

__global__ __launch_bounds__(256)
void hmma_gemm(const __nv_bfloat16* __restrict__ Aq, int lda,
               const __nv_bfloat16* __restrict__ Bq, int ldb,
               int N, int Kp,
               const float* __restrict__ bias,
               const float* __restrict__ aux, int aux_ld,
               float* __restrict__ Cf, int ldc,
               __nv_bfloat16* __restrict__ O3, int ldo,   // triple out, stride ldo*3... ldo = logical K of next layer
               int mode,
               const float* __restrict__ W0f32, const float* __restrict__ tptr)
{
    extern __shared__ char smem[];
    const uint32_t sbase = smem_u32(smem);
    const int tid = threadIdx.x;
    const int lane = tid & 31, wid = tid >> 5;
    const int bm = blockIdx.y * 128;
    const int bn = blockIdx.x * 128;
    const int warp_m = (wid & 3) * 32;
    const int warp_n = (wid >> 2) * 64;

    // ldmatrix per-lane byte offsets within a tile
    uint32_t a_off[2], b_off[4];
#pragma unroll
    for (int t = 0; t < 2; t++)
        a_off[t] = (uint32_t)(warp_m + t * 16 + (lane & 15)) * ROWB + (uint32_t)(lane >> 4) * 16;
#pragma unroll
    for (int p = 0; p < 4; p++)
        b_off[p] = (uint32_t)(warp_n + p * 16 + ((lane >> 4) << 3) + (lane & 7)) * ROWB
                 + (uint32_t)((lane >> 3) & 1) * 16;

    float acc[2][8][4];
#pragma unroll
    for (int t = 0; t < 2; t++)
#pragma unroll
        for (int j = 0; j < 8; j++)
#pragma unroll
            for (int e = 0; e < 4; e++) acc[t][j][e] = 0.0f;

    const int nch = Kp / KC;
    // loader lambda-ish via macro-free code: each thread does 4 A vecs + 4 B vecs
    const int lrow = tid >> 3;            // base row for vec id = tid (row advances by 32 per j)
    const int lkv = tid & 7;

#define ISSUE_LOADS(cc) do {                                                        \
        const int k0 = (cc) * KC;                                                   \
        const uint32_t stg = sbase + ((cc) & 1) * STAGEB;                           \
        _Pragma("unroll")                                                           \
        for (int j = 0; j < 4; j++) {                                               \
            int row = lrow + j * 32;                                                \
            uint32_t d = stg + (uint32_t)row * ROWB + (uint32_t)lkv * 16;           \
            const __nv_bfloat16* s = Aq + (size_t)(bm + row) * lda + k0 + lkv * 8;  \
            cp16(d, s, 16);                                                         \
        }                                                                           \
        _Pragma("unroll")                                                           \
        for (int j = 0; j < 4; j++) {                                               \
            int row = lrow + j * 32;                                                \
            int n0 = bn + row;                                                      \
            int nc = n0 < N ? n0 : (N - 1);                                         \
            uint32_t d = stg + TILEB + (uint32_t)row * ROWB + (uint32_t)lkv * 16;   \
            const __nv_bfloat16* s = Bq + (size_t)nc * ldb + k0 + lkv * 8;          \
            cp16(d, s, n0 < N ? 16u : 0u);                                          \
        }                                                                           \
        asm volatile("cp.async.commit_group;" ::: "memory");                        \
    } while (0)

    ISSUE_LOADS(0);

    for (int c = 0; c < nch; c++) {
        if (c + 1 < nch) {
            ISSUE_LOADS(c + 1);
            asm volatile("cp.async.wait_group 1;" ::: "memory");
        } else {
            asm volatile("cp.async.wait_group 0;" ::: "memory");
        }
        __syncthreads();

        const uint32_t sA = sbase + (c & 1) * STAGEB;
        const uint32_t sB = sA + TILEB;
#pragma unroll
        for (int ks = 0; ks < 4; ks++) {
            uint32_t a[2][4];
            ldm4(a[0][0], a[0][1], a[0][2], a[0][3], sA + a_off[0] + ks * 32);
            ldm4(a[1][0], a[1][1], a[1][2], a[1][3], sA + a_off[1] + ks * 32);
            uint32_t bb[4][4];
#pragma unroll
            for (int p = 0; p < 4; p++)
                ldm4(bb[p][0], bb[p][1], bb[p][2], bb[p][3], sB + b_off[p] + ks * 32);
#pragma unroll
            for (int t = 0; t < 2; t++)
#pragma unroll
                for (int j = 0; j < 8; j++)
                    mma16816(acc[t][j], a[t], &bb[j >> 1][(j & 1) * 2]);
        }
        __syncthreads();
    }

    // ---------------- epilogue ----------------
    float sv = 0.0f, cv = 0.0f;
    if (mode == 0) {
        float ang = tptr[0] * (2.0f * 3.14159265358979323846f / 24.0f);
        sv = sinf(ang); cv = cosf(ang);
    }
    const int mrow0 = bm + warp_m + (lane >> 2);
    const int ncol0 = bn + warp_n + (lane & 3) * 2;

#pragma unroll
    for (int t = 0; t < 2; t++)
#pragma unroll
        for (int j = 0; j < 8; j++)
#pragma unroll
            for (int half = 0; half < 2; half++) {
                int m = mrow0 + t * 16 + half * 8;
#pragma unroll
                for (int e = 0; e < 2; e++) {
                    int n = ncol0 + j * 8 + e;
                    if (n >= N) continue;
                    float v = acc[t][j][half * 2 + e] + bias[n];
                    if (mode == 0) {
                        v += sv * W0f32[(size_t)n * (Sdim + 2) + Sdim]
                           + cv * W0f32[(size_t)n * (Sdim + 2) + Sdim + 1];
                        v = fmaxf(v, 0.0f);
                    } else if (mode == 1) {
                        v = tanhf(v);
                    } else if (mode == 2) {
                        v = tanhf(aux[(size_t)m * aux_ld + n] + v);
                    } else if (mode == 5) {
                        Cf[(size_t)m * ldc + n] += 0.1f * (v - aux[(size_t)m * aux_ld + n]);
                        continue;
                    }
                    if (Cf) Cf[(size_t)m * ldc + n] = v;
                    if (O3) {
                        __nv_bfloat16 hi, lo; split_bf16(v, hi, lo);
                        size_t base = ((size_t)m * ldo + n) * 3;
                        O3[base] = hi; O3[base + 1] = hi; O3[base + 2] = lo;
                    }
                }
            }
}

// ---------------- tiny local path (Z=8, E=4) ----------------
__global__ void loc_kernel(
    const float* __restrict__ state, float* __restrict__ out,
    const float* __restrict__ loc_proj_w, const float* __restrict__ loc_proj_b,
    const float* __restrict__ lp_in_w,   const float* __restrict__ lp_in_b,
    const float* __restrict__ lp_out_w,  const float* __restrict__ lp_out_b,
    const float* __restrict__ loc_back_w,const float* __restrict__ loc_back_b)
{
    int m = blockIdx.x * blockDim.x + threadIdx.x;
    if (m >= Bsz) return;
    float loc[8];
#pragma unroll
    for (int j = 0; j < 8; j++) loc[j] = state[(size_t)m * Sdim + Adim + j];
    float lp[4];
#pragma unroll
    for (int i = 0; i < 4; i++) {
        float a = loc_proj_b[i];
#pragma unroll
        for (int j = 0; j < 8; j++) a += loc_proj_w[i * 8 + j] * loc[j];
        lp[i] = a;
    }
    float v[4];
#pragma unroll
    for (int i = 0; i < 4; i++) {
        float a = lp_in_b[8 + i];
#pragma unroll
        for (int j = 0; j < 4; j++) a += lp_in_w[(8 + i) * 4 + j] * lp[j];
        v[i] = a;
    }
    float d[4];
#pragma unroll
    for (int i = 0; i < 4; i++) {
        float a = lp_out_b[i];
#pragma unroll
        for (int j = 0; j < 4; j++) a += lp_out_w[i * 4 + j] * v[j];
        d[i] = a - lp[i];
    }
#pragma unroll
    for (int i = 0; i < 8; i++) {
        float a = loc_back_b[i];
#pragma unroll
        for (int j = 0; j < 4; j++) a += loc_back_w[i * 4 + j] * d[j];
        out[(size_t)m * Sdim + Adim + i] += 0.1f * a;
    }
}

// ---------------- launch ----------------
extern "C" void kernel_launch(void* const* d_in, const int* in_sizes, int n_in,
                              void* d_out, int out_size)
{
    const float* t          = (const float*)d_in[0];
    const float* state      = (const float*)d_in[1];
    const float* W0         = (const float*)d_in[2];
    const float* b0         = (const float*)d_in[3];
    const float* res_W1     = (const float*)d_in[4];
    const float* res_b1     = (const float*)d_in[5];
    const float* res_W2     = (const float*)d_in[6];
    const float* res_b2     = (const float*)d_in[7];
    const float* Wf         = (const float*)d_in[8];
    const float* bf         = (const float*)d_in[9];
    const float* lp_in_w    = (const float*)d_in[10];
    const float* lp_in_b    = (const float*)d_in[11];
    const float* lp_out_w   = (const float*)d_in[12];
    const float* lp_out_b   = (const float*)d_in[13];
    const float* ta_in_w    = (const float*)d_in[14];
    const float* ta_in_b    = (const float*)d_in[15];
    const float* ta_out_w   = (const float*)d_in[16];
    const float* ta_out_b   = (const float*)d_in[17];
    const float* loc_proj_w = (const float*)d_in[18];
    const float* loc_proj_b = (const float*)d_in[19];
    const float* loc_back_w = (const float*)d_in[20];
    const float* loc_back_b = (const float*)d_in[21];
    float* out = (float*)d_out;

    float* h;
    __nv_bfloat16 *sp3, *h3, *u3, *v23, *w03, *rw13, *rw23, *wf3, *tain3, *taout3;
    cudaGetSymbolAddress((void**)&h,      g_h);
    cudaGetSymbolAddress((void**)&sp3,    g_sp3);
    cudaGetSymbolAddress((void**)&h3,     g_h3);
    cudaGetSymbolAddress((void**)&u3,     g_u3);
    cudaGetSymbolAddress((void**)&v23,    g_v23);
    cudaGetSymbolAddress((void**)&w03,    g_w03);
    cudaGetSymbolAddress((void**)&rw13,   g_rw13);
    cudaGetSymbolAddress((void**)&rw23,   g_rw23);
    cudaGetSymbolAddress((void**)&wf3,    g_wf3);
    cudaGetSymbolAddress((void**)&tain3,  g_tain3);
    cudaGetSymbolAddress((void**)&taout3, g_taout3);

    cudaFuncSetAttribute(hmma_gemm, cudaFuncAttributeMaxDynamicSharedMemorySize, SMEM_DYN);

    // ---- conversions (triple interleave) ----
    {
        int tb = 256;
        conv_a<<<2048, tb>>>(state, sp3, Bsz, Sdim, Sdim, SPADK);
        conv_w<<<512,  tb>>>(W0, w03, Hdim, Sdim + 2, Sdim, SPADK);
        conv_w<<<4096, tb>>>(res_W1, rw13, Rn * Hdim, Hdim, Hdim, Hdim);
        conv_w<<<4096, tb>>>(res_W2, rw23, Rn * Hdim, Hdim, Hdim, Hdim);
        conv_w<<<1024, tb>>>(Wf, wf3, Sdim, Hdim, Hdim, Hdim);
        conv_w<<<256,  tb>>>(ta_in_w + (size_t)2 * Adim * Adim, tain3, Adim, Adim, Adim, Adim);
        conv_w<<<256,  tb>>>(ta_out_w, taout3, Adim, Adim, Adim, Adim);
    }

    const int MY = Bsz / 128; // 64
    dim3 blk(256);

    // K1: h = relu(state@W0^T + time + b0) -> h f32 + h3 triple
    hmma_gemm<<<dim3(Hdim / 128, MY), blk, SMEM_DYN>>>(
        sp3, KP_S, w03, KP_S, Hdim, KP_S,
        b0, nullptr, 0, h, Hdim, h3, Hdim, 0, W0, t);

    // residual scan
    for (int r = 0; r < Rn; r++) {
        const __nv_bfloat16* W13 = rw13 + (size_t)r * Hdim * KP_H;
        const __nv_bfloat16* W23 = rw23 + (size_t)r * Hdim * KP_H;
        const float* b1 = res_b1 + (size_t)r * Hdim;
        const float* b2 = res_b2 + (size_t)r * Hdim;
        // u = tanh(h@W1^T + b1) -> u3
        hmma_gemm<<<dim3(Hdim / 128, MY), blk, SMEM_DYN>>>(
            h3, KP_H, W13, KP_H, Hdim, KP_H,
            b1, nullptr, 0, nullptr, 0, u3, Hdim, 1, nullptr, nullptr);
        // h = tanh(h + u@W2^T + b2) -> h f32 + h3
        hmma_gemm<<<dim3(Hdim / 128, MY), blk, SMEM_DYN>>>(
            u3, KP_H, W23, KP_H, Hdim, KP_H,
            b2, h, Hdim, h, Hdim, h3, Hdim, 2, nullptr, nullptr);
    }

    // K4: out = h@Wf^T + bf (N=268)
    hmma_gemm<<<dim3((Sdim + 127) / 128, MY), blk, SMEM_DYN>>>(
        h3, KP_H, wf3, KP_H, Sdim, KP_H,
        bf, nullptr, 0, out, Sdim, nullptr, 0, 3, nullptr, nullptr);

    // K5: v2 = state[:, :256]@ta_in[512:768]^T + b -> v23 (K'=768 covers logical k<256)
    hmma_gemm<<<dim3(Adim / 128, MY), blk, SMEM_DYN>>>(
        sp3, KP_S, tain3, KP_A, Adim, KP_A,
        ta_in_b + 2 * Adim, nullptr, 0, nullptr, 0, v23, Adim, 3, nullptr, nullptr);

    // K6: out[:, :256] += 0.1*((v2@ta_out^T + b) - state[:, :256])
    hmma_gemm<<<dim3(Adim / 128, MY), blk, SMEM_DYN>>>(
        v23, KP_A, taout3, KP_A, Adim, KP_A,
        ta_out_b, state, Sdim, out, Sdim, nullptr, 0, 5, nullptr, nullptr);

    // K7: loc path
    loc_kernel<<<Bsz / 256, 256>>>(state, out,
                                   loc_proj_w, loc_proj_b,
                                   lp_in_w, lp_in_b,
                                   lp_out_w, lp_out_b,
                                   loc_back_w, loc_back_b);
}